// round 11
// baseline (speedup 1.0000x reference)
#include <cuda_runtime.h>
#include <cuda_bf16.h>
#include <cstdint>

#define NN   50000
#define EE   800000
#define ETOT (EE + NN)
#define SCANB 196

// ---------------- scratch ----------------
__device__ float g_h   [NN * 256];
__device__ float g_xw  [NN * 256];
__device__ float g_xw1 [NN * 128];
__device__ float g_al  [NN * 8];
__device__ float g_al1 [NN * 2];
__device__ __nv_bfloat16 g_xhi [NN * 256], g_xlo [NN * 256];
__device__ __nv_bfloat16 g_hhi [NN * 256], g_hlo [NN * 256];
__device__ __nv_bfloat16 g_h1hi[NN * 256], g_h1lo[NN * 256];
__device__ __nv_bfloat16 g_h2hi[NN * 128], g_h2lo[NN * 128];
__device__ __nv_bfloat16 g_WpThi[256 * 256], g_WpTlo[256 * 256];
__device__ __nv_bfloat16 g_W0Thi[256 * 256], g_W0Tlo[256 * 256];
__device__ __nv_bfloat16 g_W1Thi[128 * 256], g_W1Tlo[128 * 256];
__device__ __nv_bfloat16 g_WoThi[128 * 128], g_WoTlo[128 * 128];
__device__ int   g_count[NN];
__device__ int   g_cursor[NN];
__device__ int   g_rowstart[NN + 1];
__device__ int   g_bsum[SCANB];
__device__ int   g_esrc[ETOT];
__device__ int   g_bad;

__device__ __forceinline__ void f2hilo(float x, __nv_bfloat16& h, __nv_bfloat16& l) {
    h = __float2bfloat16(x);
    l = __float2bfloat16(x - __bfloat162float(h));
}

__device__ __forceinline__ void cpa16(uint32_t d, const void* s, int srcsz) {
    asm volatile("cp.async.cg.shared.global [%0], [%1], 16, %2;"
                 :: "r"(d), "l"(s), "r"(srcsz));
}
#define CP_COMMIT() asm volatile("cp.async.commit_group;" ::: "memory")
#define CP_WAIT0()  asm volatile("cp.async.wait_group 0;" ::: "memory")
#define CP_WAIT1()  asm volatile("cp.async.wait_group 1;" ::: "memory")

__device__ __forceinline__ void ldsm_x4(uint32_t addr, uint32_t& r0, uint32_t& r1,
                                        uint32_t& r2, uint32_t& r3) {
    asm volatile("ldmatrix.sync.aligned.m8n8.x4.shared.b16 {%0,%1,%2,%3}, [%4];"
                 : "=r"(r0), "=r"(r1), "=r"(r2), "=r"(r3) : "r"(addr));
}
__device__ __forceinline__ void mma16816(float* d, const uint32_t* a, const uint32_t* b) {
    asm volatile("mma.sync.aligned.m16n8k16.row.col.f32.bf16.bf16.f32 "
                 "{%0,%1,%2,%3}, {%4,%5,%6,%7}, {%8,%9}, {%0,%1,%2,%3};"
                 : "+f"(d[0]), "+f"(d[1]), "+f"(d[2]), "+f"(d[3])
                 : "r"(a[0]), "r"(a[1]), "r"(a[2]), "r"(a[3]), "r"(b[0]), "r"(b[1]));
}

// =====================  CSR build  =====================
__global__ void k_init() {
    int stride = gridDim.x * blockDim.x;
    int t = blockIdx.x * blockDim.x + threadIdx.x;
    for (int i = t; i < NN; i += stride) { g_count[i] = 0; g_cursor[i] = 0; }
    if (t == 0) { g_bad = 0; g_rowstart[NN] = ETOT; }
}
__global__ void k_detect(const long long* __restrict__ ei) {
    int stride = gridDim.x * blockDim.x;
    for (int e = blockIdx.x * blockDim.x + threadIdx.x; e < EE; e += stride) {
        long long v = ei[e];
        if (v < 0 || v >= NN) { g_bad = 1; return; }
    }
}
__device__ __forceinline__ int edge_at(const void* ei, int pos, int m64) {
    return m64 ? (int)((const long long*)ei)[pos] : ((const int*)ei)[pos];
}
__global__ void k_count(const void* __restrict__ ei) {
    int e = blockIdx.x * blockDim.x + threadIdx.x;
    if (e >= ETOT) return;
    int m64 = (g_bad == 0);
    int d = (e < EE) ? edge_at(ei, EE + e, m64) : (e - EE);
    atomicAdd(&g_count[d], 1);
}
__global__ void k_scan1() {
    __shared__ int wsum[8];
    int b = blockIdx.x, t = threadIdx.x;
    int idx = b * 256 + t;
    int lane = t & 31, wid = t >> 5;
    int v = (idx < NN) ? g_count[idx] : 0;
    int x = v;
#pragma unroll
    for (int off = 1; off < 32; off <<= 1) {
        int y = __shfl_up_sync(0xffffffffu, x, off);
        if (lane >= off) x += y;
    }
    if (lane == 31) wsum[wid] = x;
    __syncthreads();
    if (wid == 0) {
        int w = (lane < 8) ? wsum[lane] : 0;
#pragma unroll
        for (int off = 1; off < 8; off <<= 1) {
            int y = __shfl_up_sync(0xffffffffu, w, off);
            if (lane >= off) w += y;
        }
        if (lane < 8) wsum[lane] = w;
    }
    __syncthreads();
    int base = (wid > 0) ? wsum[wid - 1] : 0;
    if (idx < NN) g_rowstart[idx] = base + x - v;
    if (t == 255) g_bsum[b] = base + x;
}
__global__ void k_scan2() {
    __shared__ int red[8];
    __shared__ int boff;
    int b = blockIdx.x, t = threadIdx.x;
    int lane = t & 31, wid = t >> 5;
    int s = 0;
    for (int i = t; i < b; i += 256) s += g_bsum[i];
#pragma unroll
    for (int off = 16; off; off >>= 1) s += __shfl_xor_sync(0xffffffffu, s, off);
    if (lane == 0) red[wid] = s;
    __syncthreads();
    if (t == 0) {
        int tot = 0;
#pragma unroll
        for (int i = 0; i < 8; i++) tot += red[i];
        boff = tot;
    }
    __syncthreads();
    int idx = b * 256 + t;
    if (idx < NN) g_rowstart[idx] += boff;
}
__global__ void k_scatter(const void* __restrict__ ei) {
    int e = blockIdx.x * blockDim.x + threadIdx.x;
    if (e >= ETOT) return;
    int m64 = (g_bad == 0);
    int s, d;
    if (e < EE) { s = edge_at(ei, e, m64); d = edge_at(ei, EE + e, m64); }
    else        { s = d = e - EE; }
    int slot = g_rowstart[d] + atomicAdd(&g_cursor[d], 1);
    g_esrc[slot] = s;
}

// =====================  conversions  =====================
__global__ void k_cvtA(const float* __restrict__ A, __nv_bfloat16* __restrict__ hi,
                       __nv_bfloat16* __restrict__ lo, int n4) {
    int i = blockIdx.x * blockDim.x + threadIdx.x;
    if (i >= n4) return;
    float4 v = ((const float4*)A)[i];
    __nv_bfloat16 h0, h1, h2, h3, l0, l1, l2, l3;
    f2hilo(v.x, h0, l0); f2hilo(v.y, h1, l1); f2hilo(v.z, h2, l2); f2hilo(v.w, h3, l3);
    ((__nv_bfloat162*)hi)[i * 2]     = __nv_bfloat162(h0, h1);
    ((__nv_bfloat162*)hi)[i * 2 + 1] = __nv_bfloat162(h2, h3);
    ((__nv_bfloat162*)lo)[i * 2]     = __nv_bfloat162(l0, l1);
    ((__nv_bfloat162*)lo)[i * 2 + 1] = __nv_bfloat162(l2, l3);
}
__device__ __forceinline__ void cvtw1(const float* W, __nv_bfloat16* hi, __nv_bfloat16* lo,
                                      int K, int Nd, int i) {
    int k = i / Nd, n = i % Nd;
    __nv_bfloat16 h, l;
    f2hilo(W[i], h, l);
    hi[n * K + k] = h;
    lo[n * K + k] = l;
}
__global__ void k_cvtWall(const float* __restrict__ Wp, const float* __restrict__ W0,
                          const float* __restrict__ W1, const float* __restrict__ Wo) {
    int i = blockIdx.x * blockDim.x + threadIdx.x;
    if (i < 65536)        cvtw1(Wp, g_WpThi, g_WpTlo, 256, 256, i);
    else if (i < 131072)  cvtw1(W0, g_W0Thi, g_W0Tlo, 256, 256, i - 65536);
    else if (i < 163840)  cvtw1(W1, g_W1Thi, g_W1Tlo, 256, 128, i - 131072);
    else if (i < 180224)  cvtw1(Wo, g_WoThi, g_WoTlo, 128, 128, i - 163840);
}

// =====================  ldmatrix + mma.sync bf16 split GEMM  =====================
// TM = M-tile rows (128: 4m x 2n warps, 64: 2m x 4n warps). N-tile always 128.
#define LDC 132

template<bool RELU, bool BIAS, bool HILO, bool NORM, int ALH, int TM>
__global__ __launch_bounds__(256, 2)
void k_gemm_mma(const __nv_bfloat16* __restrict__ Ahi, const __nv_bfloat16* __restrict__ Alo,
                const __nv_bfloat16* __restrict__ Bhi, const __nv_bfloat16* __restrict__ Blo,
                const float* __restrict__ bias, float* __restrict__ C,
                __nv_bfloat16* __restrict__ Chi, __nv_bfloat16* __restrict__ Clo,
                const float* __restrict__ aS, const float* __restrict__ aD,
                int M, int K, int Nd) {
    constexpr int NJ   = (TM == 128) ? 4 : 2;    // 16-col B chunks per warp
    constexpr int TPR  = 256 / TM;               // epilogue threads per row
    constexpr int CPT  = 128 / TPR;              // epilogue cols per thread
    constexpr int A_B  = TM * 80;                // bytes per A limb
    constexpr int B_AHI = 0, B_ALO = A_B, B_BHI = 2 * A_B, B_BLO = 2 * A_B + 10240;
    constexpr int BUFB = 2 * A_B + 20480;

    extern __shared__ char smem[];
    const uint32_t sb0 = (uint32_t)__cvta_generic_to_shared(smem);
    float* sC  = (float*)smem;
    float* sSS = (float*)(smem + TM * LDC * 4);

    const int tid = threadIdx.x;
    const int wid = tid >> 5;
    const int lane = tid & 31;
    const int wm = (TM == 128) ? (wid & 3) : (wid & 1);
    const int wn = (TM == 128) ? (wid >> 2) : (wid >> 1);
    const int bm = blockIdx.x * TM;
    const int bn = blockIdx.y * 128;
    const int NC = K >> 5;

    uint32_t offA[2];
#pragma unroll
    for (int i = 0; i < 2; i++)
        offA[i] = (uint32_t)((wm * 32 + i * 16 + (lane & 15)) * 80 + (lane >> 4) * 16);
    uint32_t offB[NJ];
#pragma unroll
    for (int j = 0; j < NJ; j++)
        offB[j] = (uint32_t)((wn * 16 * NJ + j * 16 + (lane >> 4) * 8 + (lane & 7)) * 80 +
                             ((lane >> 3) & 1) * 16);

    float acc[2][2 * NJ][4];
#pragma unroll
    for (int i = 0; i < 2; i++)
#pragma unroll
        for (int j = 0; j < 2 * NJ; j++)
#pragma unroll
            for (int e = 0; e < 4; e++)
                acc[i][j][e] = 0.f;

    auto load_chunk = [&](int buf, int kc) {
        uint32_t sb = sb0 + buf * BUFB;
#pragma unroll
        for (int i = tid; i < 512; i += 256) {
            int r = i >> 2, seg = i & 3;
            uint32_t off = (uint32_t)(r * 80 + seg * 16);
            size_t gb = (size_t)(bn + r) * K + kc * 32 + seg * 8;
            cpa16(sb + B_BHI + off, Bhi + gb, 16);
            cpa16(sb + B_BLO + off, Blo + gb, 16);
            if (r < TM) {
                int arow = bm + r;
                int sz = (arow < M) ? 16 : 0;
                if (arow >= M) arow = M - 1;
                size_t ga = (size_t)arow * K + kc * 32 + seg * 8;
                cpa16(sb + B_AHI + off, Ahi + ga, sz);
                cpa16(sb + B_ALO + off, Alo + ga, sz);
            }
        }
    };

    load_chunk(0, 0);
    CP_COMMIT();

    for (int kc = 0; kc < NC; kc++) {
        if (kc + 1 < NC) {
            load_chunk((kc + 1) & 1, kc + 1);
            CP_COMMIT();
            CP_WAIT1();
        } else {
            CP_WAIT0();
        }
        __syncthreads();

        const uint32_t bufb = sb0 + (kc & 1) * BUFB;
#pragma unroll
        for (int ks = 0; ks < 2; ks++) {
            const uint32_t ko = (uint32_t)(ks * 32);
            uint32_t ah[2][4], al[2][4], bb[NJ][4];
#pragma unroll
            for (int i = 0; i < 2; i++) {
                ldsm_x4(bufb + B_AHI + offA[i] + ko, ah[i][0], ah[i][1], ah[i][2], ah[i][3]);
                ldsm_x4(bufb + B_ALO + offA[i] + ko, al[i][0], al[i][1], al[i][2], al[i][3]);
            }
#pragma unroll
            for (int j = 0; j < NJ; j++)
                ldsm_x4(bufb + B_BHI + offB[j] + ko, bb[j][0], bb[j][1], bb[j][2], bb[j][3]);
#pragma unroll
            for (int j = 0; j < NJ; j++)
#pragma unroll
                for (int i = 0; i < 2; i++) {
                    mma16816(acc[i][2 * j],     ah[i], &bb[j][0]);
                    mma16816(acc[i][2 * j + 1], ah[i], &bb[j][2]);
                }
#pragma unroll
            for (int j = 0; j < NJ; j++)
#pragma unroll
                for (int i = 0; i < 2; i++) {
                    mma16816(acc[i][2 * j],     al[i], &bb[j][0]);
                    mma16816(acc[i][2 * j + 1], al[i], &bb[j][2]);
                }
#pragma unroll
            for (int j = 0; j < NJ; j++)
                ldsm_x4(bufb + B_BLO + offB[j] + ko, bb[j][0], bb[j][1], bb[j][2], bb[j][3]);
#pragma unroll
            for (int j = 0; j < NJ; j++)
#pragma unroll
                for (int i = 0; i < 2; i++) {
                    mma16816(acc[i][2 * j],     ah[i], &bb[j][0]);
                    mma16816(acc[i][2 * j + 1], ah[i], &bb[j][2]);
                }
        }
        __syncthreads();
    }

    // accumulators -> SMEM C
    {
        int qr = lane >> 2, qc = (lane & 3) << 1;
#pragma unroll
        for (int i = 0; i < 2; i++)
#pragma unroll
            for (int nc = 0; nc < 2 * NJ; nc++) {
                float* p = &sC[(wm * 32 + i * 16 + qr) * LDC + wn * 16 * NJ + nc * 8 + qc];
                *(float2*)p = make_float2(acc[i][nc][0], acc[i][nc][1]);
                *(float2*)(p + 8 * LDC) = make_float2(acc[i][nc][2], acc[i][nc][3]);
            }
    }
    __syncthreads();

    // fused epilogue
    {
        int r = tid / TPR, c0 = (tid % TPR) * CPT;
        int row = bm + r;
        if (NORM) {
            if ((tid % TPR) == 0) sSS[r] = 0.f;
            __syncthreads();
            float ss = 0.f;
            if (row < M) {
#pragma unroll
                for (int j = 0; j < CPT; j += 4) {
                    float4 v = *(float4*)&sC[r * LDC + c0 + j];
                    int col = bn + c0 + j;
                    v.x += bias[col + 0]; v.y += bias[col + 1];
                    v.z += bias[col + 2]; v.w += bias[col + 3];
                    ss += v.x * v.x + v.y * v.y + v.z * v.z + v.w * v.w;
                }
            }
            atomicAdd(&sSS[r], ss);
            __syncthreads();
            if (row < M) {
                float sc = 1.f / fmaxf(sqrtf(sSS[r]), 1e-12f);
#pragma unroll
                for (int j = 0; j < CPT; j += 4) {
                    float4 v = *(float4*)&sC[r * LDC + c0 + j];
                    int col = bn + c0 + j;
                    v.x = (v.x + bias[col + 0]) * sc;
                    v.y = (v.y + bias[col + 1]) * sc;
                    v.z = (v.z + bias[col + 2]) * sc;
                    v.w = (v.w + bias[col + 3]) * sc;
                    *(float4*)&C[(size_t)row * Nd + col] = v;
                }
            }
        } else if (row < M) {
            float ps = 0.f, pd = 0.f;
#pragma unroll
            for (int j = 0; j < CPT; j += 4) {
                float4 v = *(float4*)&sC[r * LDC + c0 + j];
                int col = bn + c0 + j;
                if (BIAS) {
                    v.x += bias[col + 0]; v.y += bias[col + 1];
                    v.z += bias[col + 2]; v.w += bias[col + 3];
                }
                if (RELU) {
                    v.x = fmaxf(v.x, 0.f); v.y = fmaxf(v.y, 0.f);
                    v.z = fmaxf(v.z, 0.f); v.w = fmaxf(v.w, 0.f);
                }
                if (ALH) {
                    float4 a = *(const float4*)(aS + col);
                    float4 b = *(const float4*)(aD + col);
                    ps += v.x * a.x + v.y * a.y + v.z * a.z + v.w * a.w;
                    pd += v.x * b.x + v.y * b.y + v.z * b.z + v.w * b.w;
                }
                *(float4*)&C[(size_t)row * Nd + col] = v;
                if (HILO) {
                    __nv_bfloat16 h0, h1, h2, h3, l0, l1, l2, l3;
                    f2hilo(v.x, h0, l0); f2hilo(v.y, h1, l1);
                    f2hilo(v.z, h2, l2); f2hilo(v.w, h3, l3);
                    size_t o = (size_t)row * Nd + col;
                    *(__nv_bfloat162*)(Chi + o)     = __nv_bfloat162(h0, h1);
                    *(__nv_bfloat162*)(Chi + o + 2) = __nv_bfloat162(h2, h3);
                    *(__nv_bfloat162*)(Clo + o)     = __nv_bfloat162(l0, l1);
                    *(__nv_bfloat162*)(Clo + o + 2) = __nv_bfloat162(l2, l3);
                }
            }
            if (ALH == 4) {
                int head = (bn + c0) >> 6;
                g_al[(size_t)row * 8 + head]     = ps;
                g_al[(size_t)row * 8 + 4 + head] = pd;
            } else if (ALH == 1) {
#pragma unroll
                for (int off = TPR >> 1; off; off >>= 1) {
                    ps += __shfl_xor_sync(0xffffffffu, ps, off);
                    pd += __shfl_xor_sync(0xffffffffu, pd, off);
                }
                if ((tid % TPR) == 0) {
                    g_al1[(size_t)row * 2]     = ps;
                    g_al1[(size_t)row * 2 + 1] = pd;
                }
            }
        }
    }
}
#define SMEM_G128 (2 * (2 * 128 * 80 + 20480))   // 81920
#define SMEM_G64  (2 * (2 * 64 * 80 + 20480))    // 61440

// ============  aggregation layer 0 + fused bias/LN/residual/relu/hilo  ============
__global__ void k_agg0(const float* __restrict__ b0, const float* __restrict__ g0,
                       const float* __restrict__ be0) {
    int d = (blockIdx.x * blockDim.x + threadIdx.x) >> 5;
    int lane = threadIdx.x & 31;
    if (d >= NN) return;
    int beg = g_rowstart[d], end = g_rowstart[d + 1];
    float ald_l = g_al[d * 8 + 4 + (lane & 3)];
    int h0 = lane >> 4;
    float4 acc0 = {0, 0, 0, 0}, acc1 = {0, 0, 0, 0};
    float den0 = 0.f, den1 = 0.f;
    for (int i = beg; i < end; i += 8) {
        int ii = i + (lane >> 2);
        int s_i = 0; float w_i = 0.f;
        if (ii < end) {
            s_i = g_esrc[ii];
            float e = g_al[s_i * 8 + (lane & 3)] + ald_l;
            e = (e > 0.f) ? e : 0.2f * e;
            w_i = __expf(e);
        }
        int cnt = min(8, end - i);
        for (int k = 0; k < cnt; k++) {
            float w0 = __shfl_sync(0xffffffffu, w_i, k * 4 + h0);
            float w1 = __shfl_sync(0xffffffffu, w_i, k * 4 + 2 + h0);
            int   s  = __shfl_sync(0xffffffffu, s_i, k * 4);
            const float4* xr = (const float4*)&g_xw[(size_t)s * 256];
            float4 v0 = xr[lane], v1 = xr[32 + lane];
            acc0.x += w0 * v0.x; acc0.y += w0 * v0.y; acc0.z += w0 * v0.z; acc0.w += w0 * v0.w;
            acc1.x += w1 * v1.x; acc1.y += w1 * v1.y; acc1.z += w1 * v1.z; acc1.w += w1 * v1.w;
            den0 += w0; den1 += w1;
        }
    }
    float r0 = 1.f / den0, r1 = 1.f / den1;
    int ch0 = lane * 4, ch1 = 128 + lane * 4;
    float4 bb0 = *(const float4*)(b0 + ch0), bb1 = *(const float4*)(b0 + ch1);
    float t0[4] = {acc0.x * r0 + bb0.x, acc0.y * r0 + bb0.y, acc0.z * r0 + bb0.z, acc0.w * r0 + bb0.w};
    float t1[4] = {acc1.x * r1 + bb1.x, acc1.y * r1 + bb1.y, acc1.z * r1 + bb1.z, acc1.w * r1 + bb1.w};
    float s1 = 0.f, s2 = 0.f;
#pragma unroll
    for (int k = 0; k < 4; k++) { s1 += t0[k] + t1[k]; s2 += t0[k] * t0[k] + t1[k] * t1[k]; }
#pragma unroll
    for (int off = 16; off; off >>= 1) {
        s1 += __shfl_xor_sync(0xffffffffu, s1, off);
        s2 += __shfl_xor_sync(0xffffffffu, s2, off);
    }
    float mu = s1 * (1.f / 256.f);
    float var = s2 * (1.f / 256.f) - mu * mu;
    float rs = rsqrtf(var + 1e-5f);
    float4 gg0 = *(const float4*)(g0 + ch0),  gg1 = *(const float4*)(g0 + ch1);
    float4 ee0 = *(const float4*)(be0 + ch0), ee1 = *(const float4*)(be0 + ch1);
    const float* hr = &g_h[(size_t)d * 256];
    float4 hh0 = *(const float4*)(hr + ch0),  hh1 = *(const float4*)(hr + ch1);
    float y0[4] = {
        fmaxf((t0[0] - mu) * rs * gg0.x + ee0.x + hh0.x, 0.f),
        fmaxf((t0[1] - mu) * rs * gg0.y + ee0.y + hh0.y, 0.f),
        fmaxf((t0[2] - mu) * rs * gg0.z + ee0.z + hh0.z, 0.f),
        fmaxf((t0[3] - mu) * rs * gg0.w + ee0.w + hh0.w, 0.f)};
    float y1[4] = {
        fmaxf((t1[0] - mu) * rs * gg1.x + ee1.x + hh1.x, 0.f),
        fmaxf((t1[1] - mu) * rs * gg1.y + ee1.y + hh1.y, 0.f),
        fmaxf((t1[2] - mu) * rs * gg1.z + ee1.z + hh1.z, 0.f),
        fmaxf((t1[3] - mu) * rs * gg1.w + ee1.w + hh1.w, 0.f)};
    __nv_bfloat16 h[8], l[8];
#pragma unroll
    for (int k = 0; k < 4; k++) { f2hilo(y0[k], h[k], l[k]); f2hilo(y1[k], h[4 + k], l[4 + k]); }
    size_t o0 = (size_t)d * 256 + ch0, o1 = (size_t)d * 256 + ch1;
    *(__nv_bfloat162*)(g_h1hi + o0)     = __nv_bfloat162(h[0], h[1]);
    *(__nv_bfloat162*)(g_h1hi + o0 + 2) = __nv_bfloat162(h[2], h[3]);
    *(__nv_bfloat162*)(g_h1hi + o1)     = __nv_bfloat162(h[4], h[5]);
    *(__nv_bfloat162*)(g_h1hi + o1 + 2) = __nv_bfloat162(h[6], h[7]);
    *(__nv_bfloat162*)(g_h1lo + o0)     = __nv_bfloat162(l[0], l[1]);
    *(__nv_bfloat162*)(g_h1lo + o0 + 2) = __nv_bfloat162(l[2], l[3]);
    *(__nv_bfloat162*)(g_h1lo + o1)     = __nv_bfloat162(l[4], l[5]);
    *(__nv_bfloat162*)(g_h1lo + o1 + 2) = __nv_bfloat162(l[6], l[7]);
}

// ============  aggregation layer 1 + fused bias/LN/hilo  ============
__global__ void k_agg1(const float* __restrict__ b1, const float* __restrict__ g1,
                       const float* __restrict__ be1) {
    int d = (blockIdx.x * blockDim.x + threadIdx.x) >> 5;
    int lane = threadIdx.x & 31;
    if (d >= NN) return;
    int beg = g_rowstart[d], end = g_rowstart[d + 1];
    float ald = g_al1[d * 2 + 1];
    float4 acc = {0, 0, 0, 0};
    float den_l = 0.f;
    for (int i = beg; i < end; i += 32) {
        int ii = i + lane;
        int s_i = 0; float w_i = 0.f;
        if (ii < end) {
            s_i = g_esrc[ii];
            float e = g_al1[s_i * 2] + ald;
            e = (e > 0.f) ? e : 0.2f * e;
            w_i = __expf(e);
            den_l += w_i;
        }
        int cnt = min(32, end - i);
        for (int k = 0; k < cnt; k++) {
            float w = __shfl_sync(0xffffffffu, w_i, k);
            int   s = __shfl_sync(0xffffffffu, s_i, k);
            float4 v = *(const float4*)&g_xw1[(size_t)s * 128 + lane * 4];
            acc.x += w * v.x; acc.y += w * v.y; acc.z += w * v.z; acc.w += w * v.w;
        }
    }
    float den = den_l;
#pragma unroll
    for (int off = 16; off; off >>= 1)
        den += __shfl_xor_sync(0xffffffffu, den, off);
    float r = 1.f / den;
    int ch = lane * 4;
    float4 bb = *(const float4*)(b1 + ch);
    float t[4] = {acc.x * r + bb.x, acc.y * r + bb.y, acc.z * r + bb.z, acc.w * r + bb.w};
    float s1 = 0.f, s2 = 0.f;
#pragma unroll
    for (int k = 0; k < 4; k++) { s1 += t[k]; s2 += t[k] * t[k]; }
#pragma unroll
    for (int off = 16; off; off >>= 1) {
        s1 += __shfl_xor_sync(0xffffffffu, s1, off);
        s2 += __shfl_xor_sync(0xffffffffu, s2, off);
    }
    float mu = s1 * (1.f / 128.f);
    float var = s2 * (1.f / 128.f) - mu * mu;
    float rs = rsqrtf(var + 1e-5f);
    float4 gg = *(const float4*)(g1 + ch);
    float4 ee = *(const float4*)(be1 + ch);
    float y[4] = {
        (t[0] - mu) * rs * gg.x + ee.x, (t[1] - mu) * rs * gg.y + ee.y,
        (t[2] - mu) * rs * gg.z + ee.z, (t[3] - mu) * rs * gg.w + ee.w};
    __nv_bfloat16 h[4], l[4];
#pragma unroll
    for (int k = 0; k < 4; k++) f2hilo(y[k], h[k], l[k]);
    size_t o = (size_t)d * 128 + ch;
    *(__nv_bfloat162*)(g_h2hi + o)     = __nv_bfloat162(h[0], h[1]);
    *(__nv_bfloat162*)(g_h2hi + o + 2) = __nv_bfloat162(h[2], h[3]);
    *(__nv_bfloat162*)(g_h2lo + o)     = __nv_bfloat162(l[0], l[1]);
    *(__nv_bfloat162*)(g_h2lo + o + 2) = __nv_bfloat162(l[2], l[3]);
}

// =====================  launch  =====================
extern "C" void kernel_launch(void* const* d_in, const int* in_sizes, int n_in,
                              void* d_out, int out_size) {
    const float* x   = (const float*)d_in[0];
    const void*  ei  = d_in[1];
    const float* Wp  = (const float*)d_in[2];
    const float* bp  = (const float*)d_in[3];
    const float* W0  = (const float*)d_in[4];
    const float* as0 = (const float*)d_in[5];
    const float* ad0 = (const float*)d_in[6];
    const float* b0  = (const float*)d_in[7];
    const float* W1  = (const float*)d_in[8];
    const float* as1 = (const float*)d_in[9];
    const float* ad1 = (const float*)d_in[10];
    const float* b1  = (const float*)d_in[11];
    const float* g0  = (const float*)d_in[12];
    const float* be0 = (const float*)d_in[13];
    const float* g1  = (const float*)d_in[14];
    const float* be1 = (const float*)d_in[15];
    const float* Wo  = (const float*)d_in[16];
    const float* bo  = (const float*)d_in[17];
    float* out = (float*)d_out;

    void *p_h, *p_xw, *p_xw1;
    void *p_xhi, *p_xlo, *p_hhi, *p_hlo, *p_h1hi, *p_h1lo, *p_h2hi, *p_h2lo;
    void *p_WpThi, *p_WpTlo, *p_W0Thi, *p_W0Tlo, *p_W1Thi, *p_W1Tlo, *p_WoThi, *p_WoTlo;
    cudaGetSymbolAddress(&p_h,    g_h);
    cudaGetSymbolAddress(&p_xw,   g_xw);
    cudaGetSymbolAddress(&p_xw1,  g_xw1);
    cudaGetSymbolAddress(&p_xhi,  g_xhi);   cudaGetSymbolAddress(&p_xlo,  g_xlo);
    cudaGetSymbolAddress(&p_hhi,  g_hhi);   cudaGetSymbolAddress(&p_hlo,  g_hlo);
    cudaGetSymbolAddress(&p_h1hi, g_h1hi);  cudaGetSymbolAddress(&p_h1lo, g_h1lo);
    cudaGetSymbolAddress(&p_h2hi, g_h2hi);  cudaGetSymbolAddress(&p_h2lo, g_h2lo);
    cudaGetSymbolAddress(&p_WpThi, g_WpThi); cudaGetSymbolAddress(&p_WpTlo, g_WpTlo);
    cudaGetSymbolAddress(&p_W0Thi, g_W0Thi); cudaGetSymbolAddress(&p_W0Tlo, g_W0Tlo);
    cudaGetSymbolAddress(&p_W1Thi, g_W1Thi); cudaGetSymbolAddress(&p_W1Tlo, g_W1Tlo);
    cudaGetSymbolAddress(&p_WoThi, g_WoThi); cudaGetSymbolAddress(&p_WoTlo, g_WoTlo);

    const int nodeBlocks = (NN + 7) / 8;
    const int edgeBlocks = (ETOT + 255) / 256;
    const int gB128 = (NN + 127) / 128;
    const int gB64  = (NN + 63) / 64;

    cudaFuncSetAttribute((const void*)k_gemm_mma<true,  true,  true,  false, 0, 128>,
                         cudaFuncAttributeMaxDynamicSharedMemorySize, SMEM_G128);
    cudaFuncSetAttribute((const void*)k_gemm_mma<false, false, false, false, 4, 128>,
                         cudaFuncAttributeMaxDynamicSharedMemorySize, SMEM_G128);
    cudaFuncSetAttribute((const void*)k_gemm_mma<false, false, false, false, 1, 64>,
                         cudaFuncAttributeMaxDynamicSharedMemorySize, SMEM_G64);
    cudaFuncSetAttribute((const void*)k_gemm_mma<false, true,  false, true,  0, 64>,
                         cudaFuncAttributeMaxDynamicSharedMemorySize, SMEM_G64);

    // side stream for CSR build (overlaps GEMM1/GEMM2); falls back to serial
    cudaStream_t s2 = 0;
    cudaEvent_t e1 = 0, e2 = 0;
    bool forked =
        cudaStreamCreateWithFlags(&s2, cudaStreamNonBlocking) == cudaSuccess &&
        cudaEventCreateWithFlags(&e1, cudaEventDisableTiming) == cudaSuccess &&
        cudaEventCreateWithFlags(&e2, cudaEventDisableTiming) == cudaSuccess;
    if (forked) {
        if (cudaEventRecord(e1, 0) != cudaSuccess ||
            cudaStreamWaitEvent(s2, e1, 0) != cudaSuccess)
            forked = false;
    }
    cudaStream_t sc = forked ? s2 : 0;

    // main chain: conversions -> GEMM1 -> GEMM2 (GEMM2 is profiled slot #4)
    k_cvtA<<<(NN * 64 + 255) / 256, 256>>>(x, (__nv_bfloat16*)p_xhi, (__nv_bfloat16*)p_xlo, NN * 64);
    k_cvtWall<<<(180224 + 255) / 256, 256>>>(Wp, W0, W1, Wo);

    k_gemm_mma<true, true, true, false, 0, 128><<<dim3(gB128, 2), 256, SMEM_G128>>>(
        (const __nv_bfloat16*)p_xhi, (const __nv_bfloat16*)p_xlo,
        (const __nv_bfloat16*)p_WpThi, (const __nv_bfloat16*)p_WpTlo,
        bp, (float*)p_h, (__nv_bfloat16*)p_hhi, (__nv_bfloat16*)p_hlo,
        nullptr, nullptr, NN, 256, 256);

    k_gemm_mma<false, false, false, false, 4, 128><<<dim3(gB128, 2), 256, SMEM_G128>>>(
        (const __nv_bfloat16*)p_hhi, (const __nv_bfloat16*)p_hlo,
        (const __nv_bfloat16*)p_W0Thi, (const __nv_bfloat16*)p_W0Tlo,
        nullptr, (float*)p_xw, nullptr, nullptr, as0, ad0, NN, 256, 256);

    // CSR build (concurrent with GEMM1/GEMM2 when forked)
    k_init<<<400, 256, 0, sc>>>();
    k_detect<<<400, 256, 0, sc>>>((const long long*)ei);
    k_count<<<edgeBlocks, 256, 0, sc>>>(ei);
    k_scan1<<<SCANB, 256, 0, sc>>>();
    k_scan2<<<SCANB, 256, 0, sc>>>();
    k_scatter<<<edgeBlocks, 256, 0, sc>>>(ei);
    if (forked) {
        cudaEventRecord(e2, s2);
        cudaStreamWaitEvent(0, e2, 0);
    }

    // agg0 + LN0 + residual + relu -> h1 hi/lo
    k_agg0<<<nodeBlocks, 256>>>(b0, g0, be0);

    // GEMM3 (64-row tiles): xw1 = h1@W1, logits al1 fused
    k_gemm_mma<false, false, false, false, 1, 64><<<dim3(gB64, 1), 256, SMEM_G64>>>(
        (const __nv_bfloat16*)p_h1hi, (const __nv_bfloat16*)p_h1lo,
        (const __nv_bfloat16*)p_W1Thi, (const __nv_bfloat16*)p_W1Tlo,
        nullptr, (float*)p_xw1, nullptr, nullptr, as1, ad1, NN, 256, 128);

    // agg1 + LN1 -> h2 hi/lo
    k_agg1<<<nodeBlocks, 256>>>(b1, g1, be1);

    // GEMM4 (64-row tiles): out = rownorm(h2@Wo + bo)
    k_gemm_mma<false, true, false, true, 0, 64><<<dim3(gB64, 1), 256, SMEM_G64>>>(
        (const __nv_bfloat16*)p_h2hi, (const __nv_bfloat16*)p_h2lo,
        (const __nv_bfloat16*)p_WoThi, (const __nv_bfloat16*)p_WoTlo,
        bo, out, nullptr, nullptr, nullptr, nullptr, NN, 128, 128);
}

// round 12
// speedup vs baseline: 1.4965x; 1.4965x over previous
#include <cuda_runtime.h>
#include <cuda_bf16.h>
#include <cstdint>

#define NN   50000
#define EE   800000
#define ETOT (EE + NN)
#define SCANB 196

// ---------------- scratch ----------------
__device__ float g_xw  [NN * 256];
__device__ float g_xw1 [NN * 128];
__device__ float g_al  [NN * 8];
__device__ float g_al1 [NN * 2];
__device__ __nv_bfloat16 g_xhi [NN * 256], g_xlo [NN * 256];
__device__ __nv_bfloat16 g_hhi [NN * 256], g_hlo [NN * 256];
__device__ __nv_bfloat16 g_h1hi[NN * 256], g_h1lo[NN * 256];
__device__ __nv_bfloat16 g_h2hi[NN * 128], g_h2lo[NN * 128];
__device__ __nv_bfloat16 g_WpThi[256 * 256], g_WpTlo[256 * 256];
__device__ __nv_bfloat16 g_W0Thi[256 * 256], g_W0Tlo[256 * 256];
__device__ __nv_bfloat16 g_W1Thi[128 * 256], g_W1Tlo[128 * 256];
__device__ __nv_bfloat16 g_WoThi[128 * 128], g_WoTlo[128 * 128];
__device__ int   g_count[NN];
__device__ int   g_cursor[NN];
__device__ int   g_rowstart[NN + 1];
__device__ int   g_bsum[SCANB];
__device__ int   g_esrc[ETOT];
__device__ int   g_bad;

__device__ __forceinline__ void f2hilo(float x, __nv_bfloat16& h, __nv_bfloat16& l) {
    h = __float2bfloat16(x);
    l = __float2bfloat16(x - __bfloat162float(h));
}

__device__ __forceinline__ void cpa16(uint32_t d, const void* s, int srcsz) {
    asm volatile("cp.async.cg.shared.global [%0], [%1], 16, %2;"
                 :: "r"(d), "l"(s), "r"(srcsz));
}
#define CP_COMMIT() asm volatile("cp.async.commit_group;" ::: "memory")
#define CP_WAIT0()  asm volatile("cp.async.wait_group 0;" ::: "memory")
#define CP_WAIT1()  asm volatile("cp.async.wait_group 1;" ::: "memory")

__device__ __forceinline__ void ldsm_x4(uint32_t addr, uint32_t& r0, uint32_t& r1,
                                        uint32_t& r2, uint32_t& r3) {
    asm volatile("ldmatrix.sync.aligned.m8n8.x4.shared.b16 {%0,%1,%2,%3}, [%4];"
                 : "=r"(r0), "=r"(r1), "=r"(r2), "=r"(r3) : "r"(addr));
}
__device__ __forceinline__ void mma16816(float* d, const uint32_t* a, const uint32_t* b) {
    asm volatile("mma.sync.aligned.m16n8k16.row.col.f32.bf16.bf16.f32 "
                 "{%0,%1,%2,%3}, {%4,%5,%6,%7}, {%8,%9}, {%0,%1,%2,%3};"
                 : "+f"(d[0]), "+f"(d[1]), "+f"(d[2]), "+f"(d[3])
                 : "r"(a[0]), "r"(a[1]), "r"(a[2]), "r"(a[3]), "r"(b[0]), "r"(b[1]));
}

// =====================  CSR build  =====================
__global__ void k_init() {
    int stride = gridDim.x * blockDim.x;
    int t = blockIdx.x * blockDim.x + threadIdx.x;
    for (int i = t; i < NN; i += stride) { g_count[i] = 0; g_cursor[i] = 0; }
    if (t == 0) { g_bad = 0; g_rowstart[NN] = ETOT; }
}
__global__ void k_detect(const long long* __restrict__ ei) {
    int stride = gridDim.x * blockDim.x;
    for (int e = blockIdx.x * blockDim.x + threadIdx.x; e < EE; e += stride) {
        long long v = ei[e];
        if (v < 0 || v >= NN) { g_bad = 1; return; }
    }
}
__device__ __forceinline__ int edge_at(const void* ei, int pos, int m64) {
    return m64 ? (int)((const long long*)ei)[pos] : ((const int*)ei)[pos];
}
__global__ void k_count(const void* __restrict__ ei) {
    int e = blockIdx.x * blockDim.x + threadIdx.x;
    if (e >= ETOT) return;
    int m64 = (g_bad == 0);
    int d = (e < EE) ? edge_at(ei, EE + e, m64) : (e - EE);
    atomicAdd(&g_count[d], 1);
}
__global__ void k_scan1() {
    __shared__ int wsum[8];
    int b = blockIdx.x, t = threadIdx.x;
    int idx = b * 256 + t;
    int lane = t & 31, wid = t >> 5;
    int v = (idx < NN) ? g_count[idx] : 0;
    int x = v;
#pragma unroll
    for (int off = 1; off < 32; off <<= 1) {
        int y = __shfl_up_sync(0xffffffffu, x, off);
        if (lane >= off) x += y;
    }
    if (lane == 31) wsum[wid] = x;
    __syncthreads();
    if (wid == 0) {
        int w = (lane < 8) ? wsum[lane] : 0;
#pragma unroll
        for (int off = 1; off < 8; off <<= 1) {
            int y = __shfl_up_sync(0xffffffffu, w, off);
            if (lane >= off) w += y;
        }
        if (lane < 8) wsum[lane] = w;
    }
    __syncthreads();
    int base = (wid > 0) ? wsum[wid - 1] : 0;
    if (idx < NN) g_rowstart[idx] = base + x - v;
    if (t == 255) g_bsum[b] = base + x;
}
__global__ void k_scan2() {
    __shared__ int red[8];
    __shared__ int boff;
    int b = blockIdx.x, t = threadIdx.x;
    int lane = t & 31, wid = t >> 5;
    int s = 0;
    for (int i = t; i < b; i += 256) s += g_bsum[i];
#pragma unroll
    for (int off = 16; off; off >>= 1) s += __shfl_xor_sync(0xffffffffu, s, off);
    if (lane == 0) red[wid] = s;
    __syncthreads();
    if (t == 0) {
        int tot = 0;
#pragma unroll
        for (int i = 0; i < 8; i++) tot += red[i];
        boff = tot;
    }
    __syncthreads();
    int idx = b * 256 + t;
    if (idx < NN) g_rowstart[idx] += boff;
}
__global__ void k_scatter(const void* __restrict__ ei) {
    int e = blockIdx.x * blockDim.x + threadIdx.x;
    if (e >= ETOT) return;
    int m64 = (g_bad == 0);
    int s, d;
    if (e < EE) { s = edge_at(ei, e, m64); d = edge_at(ei, EE + e, m64); }
    else        { s = d = e - EE; }
    int slot = g_rowstart[d] + atomicAdd(&g_cursor[d], 1);
    g_esrc[slot] = s;
}

// =====================  conversions  =====================
__global__ void k_cvtA(const float* __restrict__ A, __nv_bfloat16* __restrict__ hi,
                       __nv_bfloat16* __restrict__ lo, int n4) {
    int i = blockIdx.x * blockDim.x + threadIdx.x;
    if (i >= n4) return;
    float4 v = ((const float4*)A)[i];
    __nv_bfloat16 h0, h1, h2, h3, l0, l1, l2, l3;
    f2hilo(v.x, h0, l0); f2hilo(v.y, h1, l1); f2hilo(v.z, h2, l2); f2hilo(v.w, h3, l3);
    ((__nv_bfloat162*)hi)[i * 2]     = __nv_bfloat162(h0, h1);
    ((__nv_bfloat162*)hi)[i * 2 + 1] = __nv_bfloat162(h2, h3);
    ((__nv_bfloat162*)lo)[i * 2]     = __nv_bfloat162(l0, l1);
    ((__nv_bfloat162*)lo)[i * 2 + 1] = __nv_bfloat162(l2, l3);
}
__device__ __forceinline__ void cvtw1(const float* W, __nv_bfloat16* hi, __nv_bfloat16* lo,
                                      int K, int Nd, int i) {
    int k = i / Nd, n = i % Nd;
    __nv_bfloat16 h, l;
    f2hilo(W[i], h, l);
    hi[n * K + k] = h;
    lo[n * K + k] = l;
}
__global__ void k_cvtWall(const float* __restrict__ Wp, const float* __restrict__ W0,
                          const float* __restrict__ W1, const float* __restrict__ Wo) {
    int i = blockIdx.x * blockDim.x + threadIdx.x;
    if (i < 65536)        cvtw1(Wp, g_WpThi, g_WpTlo, 256, 256, i);
    else if (i < 131072)  cvtw1(W0, g_W0Thi, g_W0Tlo, 256, 256, i - 65536);
    else if (i < 163840)  cvtw1(W1, g_W1Thi, g_W1Tlo, 256, 128, i - 131072);
    else if (i < 180224)  cvtw1(Wo, g_WoThi, g_WoTlo, 128, 128, i - 163840);
}

// =====================  ldmatrix + mma.sync bf16 split GEMM  =====================
#define LDC 132

template<bool RELU, bool BIAS, bool HILO, bool NORM, int ALH, int TM>
__global__ __launch_bounds__(256, 2)
void k_gemm_mma(const __nv_bfloat16* __restrict__ Ahi, const __nv_bfloat16* __restrict__ Alo,
                const __nv_bfloat16* __restrict__ Bhi, const __nv_bfloat16* __restrict__ Blo,
                const float* __restrict__ bias, float* __restrict__ C,
                __nv_bfloat16* __restrict__ Chi, __nv_bfloat16* __restrict__ Clo,
                const float* __restrict__ aS, const float* __restrict__ aD,
                int M, int K, int Nd) {
    constexpr int NJ   = (TM == 128) ? 4 : 2;
    constexpr int TPR  = 256 / TM;
    constexpr int CPT  = 128 / TPR;
    constexpr int A_B  = TM * 80;
    constexpr int B_AHI = 0, B_ALO = A_B, B_BHI = 2 * A_B, B_BLO = 2 * A_B + 10240;
    constexpr int BUFB = 2 * A_B + 20480;

    extern __shared__ char smem[];
    const uint32_t sb0 = (uint32_t)__cvta_generic_to_shared(smem);
    float* sC  = (float*)smem;
    float* sSS = (float*)(smem + TM * LDC * 4);

    const int tid = threadIdx.x;
    const int wid = tid >> 5;
    const int lane = tid & 31;
    const int wm = (TM == 128) ? (wid & 3) : (wid & 1);
    const int wn = (TM == 128) ? (wid >> 2) : (wid >> 1);
    const int bm = blockIdx.x * TM;
    const int bn = blockIdx.y * 128;
    const int NC = K >> 5;

    uint32_t offA[2];
#pragma unroll
    for (int i = 0; i < 2; i++)
        offA[i] = (uint32_t)((wm * 32 + i * 16 + (lane & 15)) * 80 + (lane >> 4) * 16);
    uint32_t offB[NJ];
#pragma unroll
    for (int j = 0; j < NJ; j++)
        offB[j] = (uint32_t)((wn * 16 * NJ + j * 16 + (lane >> 4) * 8 + (lane & 7)) * 80 +
                             ((lane >> 3) & 1) * 16);

    float acc[2][2 * NJ][4];
#pragma unroll
    for (int i = 0; i < 2; i++)
#pragma unroll
        for (int j = 0; j < 2 * NJ; j++)
#pragma unroll
            for (int e = 0; e < 4; e++)
                acc[i][j][e] = 0.f;

    auto load_chunk = [&](int buf, int kc) {
        uint32_t sb = sb0 + buf * BUFB;
#pragma unroll
        for (int i = tid; i < 512; i += 256) {
            int r = i >> 2, seg = i & 3;
            uint32_t off = (uint32_t)(r * 80 + seg * 16);
            size_t gb = (size_t)(bn + r) * K + kc * 32 + seg * 8;
            cpa16(sb + B_BHI + off, Bhi + gb, 16);
            cpa16(sb + B_BLO + off, Blo + gb, 16);
            if (r < TM) {
                int arow = bm + r;
                int sz = (arow < M) ? 16 : 0;
                if (arow >= M) arow = M - 1;
                size_t ga = (size_t)arow * K + kc * 32 + seg * 8;
                cpa16(sb + B_AHI + off, Ahi + ga, sz);
                cpa16(sb + B_ALO + off, Alo + ga, sz);
            }
        }
    };

    load_chunk(0, 0);
    CP_COMMIT();

    for (int kc = 0; kc < NC; kc++) {
        if (kc + 1 < NC) {
            load_chunk((kc + 1) & 1, kc + 1);
            CP_COMMIT();
            CP_WAIT1();
        } else {
            CP_WAIT0();
        }
        __syncthreads();

        const uint32_t bufb = sb0 + (kc & 1) * BUFB;
#pragma unroll
        for (int ks = 0; ks < 2; ks++) {
            const uint32_t ko = (uint32_t)(ks * 32);
            uint32_t ah[2][4], al[2][4], bb[NJ][4];
#pragma unroll
            for (int i = 0; i < 2; i++) {
                ldsm_x4(bufb + B_AHI + offA[i] + ko, ah[i][0], ah[i][1], ah[i][2], ah[i][3]);
                ldsm_x4(bufb + B_ALO + offA[i] + ko, al[i][0], al[i][1], al[i][2], al[i][3]);
            }
#pragma unroll
            for (int j = 0; j < NJ; j++)
                ldsm_x4(bufb + B_BHI + offB[j] + ko, bb[j][0], bb[j][1], bb[j][2], bb[j][3]);
#pragma unroll
            for (int j = 0; j < NJ; j++)
#pragma unroll
                for (int i = 0; i < 2; i++) {
                    mma16816(acc[i][2 * j],     ah[i], &bb[j][0]);
                    mma16816(acc[i][2 * j + 1], ah[i], &bb[j][2]);
                }
#pragma unroll
            for (int j = 0; j < NJ; j++)
#pragma unroll
                for (int i = 0; i < 2; i++) {
                    mma16816(acc[i][2 * j],     al[i], &bb[j][0]);
                    mma16816(acc[i][2 * j + 1], al[i], &bb[j][2]);
                }
#pragma unroll
            for (int j = 0; j < NJ; j++)
                ldsm_x4(bufb + B_BLO + offB[j] + ko, bb[j][0], bb[j][1], bb[j][2], bb[j][3]);
#pragma unroll
            for (int j = 0; j < NJ; j++)
#pragma unroll
                for (int i = 0; i < 2; i++) {
                    mma16816(acc[i][2 * j],     ah[i], &bb[j][0]);
                    mma16816(acc[i][2 * j + 1], ah[i], &bb[j][2]);
                }
        }
        __syncthreads();
    }

    // accumulators -> SMEM C
    {
        int qr = lane >> 2, qc = (lane & 3) << 1;
#pragma unroll
        for (int i = 0; i < 2; i++)
#pragma unroll
            for (int nc = 0; nc < 2 * NJ; nc++) {
                float* p = &sC[(wm * 32 + i * 16 + qr) * LDC + wn * 16 * NJ + nc * 8 + qc];
                *(float2*)p = make_float2(acc[i][nc][0], acc[i][nc][1]);
                *(float2*)(p + 8 * LDC) = make_float2(acc[i][nc][2], acc[i][nc][3]);
            }
    }
    __syncthreads();

    // fused epilogue
    {
        int r = tid / TPR, c0 = (tid % TPR) * CPT;
        int row = bm + r;
        if (NORM) {
            if ((tid % TPR) == 0) sSS[r] = 0.f;
            __syncthreads();
            float ss = 0.f;
            if (row < M) {
#pragma unroll
                for (int j = 0; j < CPT; j += 4) {
                    float4 v = *(float4*)&sC[r * LDC + c0 + j];
                    int col = bn + c0 + j;
                    v.x += bias[col + 0]; v.y += bias[col + 1];
                    v.z += bias[col + 2]; v.w += bias[col + 3];
                    ss += v.x * v.x + v.y * v.y + v.z * v.z + v.w * v.w;
                }
            }
            atomicAdd(&sSS[r], ss);
            __syncthreads();
            if (row < M) {
                float sc = 1.f / fmaxf(sqrtf(sSS[r]), 1e-12f);
#pragma unroll
                for (int j = 0; j < CPT; j += 4) {
                    float4 v = *(float4*)&sC[r * LDC + c0 + j];
                    int col = bn + c0 + j;
                    v.x = (v.x + bias[col + 0]) * sc;
                    v.y = (v.y + bias[col + 1]) * sc;
                    v.z = (v.z + bias[col + 2]) * sc;
                    v.w = (v.w + bias[col + 3]) * sc;
                    *(float4*)&C[(size_t)row * Nd + col] = v;
                }
            }
        } else if (row < M) {
            float ps = 0.f, pd = 0.f;
#pragma unroll
            for (int j = 0; j < CPT; j += 4) {
                float4 v = *(float4*)&sC[r * LDC + c0 + j];
                int col = bn + c0 + j;
                if (BIAS) {
                    v.x += bias[col + 0]; v.y += bias[col + 1];
                    v.z += bias[col + 2]; v.w += bias[col + 3];
                }
                if (RELU) {
                    v.x = fmaxf(v.x, 0.f); v.y = fmaxf(v.y, 0.f);
                    v.z = fmaxf(v.z, 0.f); v.w = fmaxf(v.w, 0.f);
                }
                if (ALH) {
                    float4 a = *(const float4*)(aS + col);
                    float4 b = *(const float4*)(aD + col);
                    ps += v.x * a.x + v.y * a.y + v.z * a.z + v.w * a.w;
                    pd += v.x * b.x + v.y * b.y + v.z * b.z + v.w * b.w;
                }
                if (C) *(float4*)&C[(size_t)row * Nd + col] = v;
                if (HILO) {
                    __nv_bfloat16 h0, h1, h2, h3, l0, l1, l2, l3;
                    f2hilo(v.x, h0, l0); f2hilo(v.y, h1, l1);
                    f2hilo(v.z, h2, l2); f2hilo(v.w, h3, l3);
                    size_t o = (size_t)row * Nd + col;
                    *(__nv_bfloat162*)(Chi + o)     = __nv_bfloat162(h0, h1);
                    *(__nv_bfloat162*)(Chi + o + 2) = __nv_bfloat162(h2, h3);
                    *(__nv_bfloat162*)(Clo + o)     = __nv_bfloat162(l0, l1);
                    *(__nv_bfloat162*)(Clo + o + 2) = __nv_bfloat162(l2, l3);
                }
            }
            if (ALH == 4) {
                int head = (bn + c0) >> 6;
                g_al[(size_t)row * 8 + head]     = ps;
                g_al[(size_t)row * 8 + 4 + head] = pd;
            } else if (ALH == 1) {
#pragma unroll
                for (int off = TPR >> 1; off; off >>= 1) {
                    ps += __shfl_xor_sync(0xffffffffu, ps, off);
                    pd += __shfl_xor_sync(0xffffffffu, pd, off);
                }
                if ((tid % TPR) == 0) {
                    g_al1[(size_t)row * 2]     = ps;
                    g_al1[(size_t)row * 2 + 1] = pd;
                }
            }
        }
    }
}
#define SMEM_G128 (2 * (2 * 128 * 80 + 20480))   // 81920
#define SMEM_G64  (2 * (2 * 64 * 80 + 20480))    // 61440

// ============  aggregation layer 0 + fused bias/LN/residual/relu/hilo  ============
// residual h reconstructed exactly from g_hhi + g_hlo
__global__ void k_agg0(const float* __restrict__ b0, const float* __restrict__ g0,
                       const float* __restrict__ be0) {
    int d = (blockIdx.x * blockDim.x + threadIdx.x) >> 5;
    int lane = threadIdx.x & 31;
    if (d >= NN) return;
    int beg = g_rowstart[d], end = g_rowstart[d + 1];
    float ald_l = g_al[d * 8 + 4 + (lane & 3)];
    int h0i = lane >> 4;
    float4 acc0 = {0, 0, 0, 0}, acc1 = {0, 0, 0, 0};
    float den0 = 0.f, den1 = 0.f;
    for (int i = beg; i < end; i += 8) {
        int ii = i + (lane >> 2);
        int s_i = 0; float w_i = 0.f;
        if (ii < end) {
            s_i = g_esrc[ii];
            float e = g_al[s_i * 8 + (lane & 3)] + ald_l;
            e = (e > 0.f) ? e : 0.2f * e;
            w_i = __expf(e);
        }
        int cnt = min(8, end - i);
        for (int k = 0; k < cnt; k++) {
            float w0 = __shfl_sync(0xffffffffu, w_i, k * 4 + h0i);
            float w1 = __shfl_sync(0xffffffffu, w_i, k * 4 + 2 + h0i);
            int   s  = __shfl_sync(0xffffffffu, s_i, k * 4);
            const float4* xr = (const float4*)&g_xw[(size_t)s * 256];
            float4 v0 = xr[lane], v1 = xr[32 + lane];
            acc0.x += w0 * v0.x; acc0.y += w0 * v0.y; acc0.z += w0 * v0.z; acc0.w += w0 * v0.w;
            acc1.x += w1 * v1.x; acc1.y += w1 * v1.y; acc1.z += w1 * v1.z; acc1.w += w1 * v1.w;
            den0 += w0; den1 += w1;
        }
    }
    float r0 = 1.f / den0, r1 = 1.f / den1;
    int ch0 = lane * 4, ch1 = 128 + lane * 4;
    float4 bb0 = *(const float4*)(b0 + ch0), bb1 = *(const float4*)(b0 + ch1);
    float t0[4] = {acc0.x * r0 + bb0.x, acc0.y * r0 + bb0.y, acc0.z * r0 + bb0.z, acc0.w * r0 + bb0.w};
    float t1[4] = {acc1.x * r1 + bb1.x, acc1.y * r1 + bb1.y, acc1.z * r1 + bb1.z, acc1.w * r1 + bb1.w};
    float s1 = 0.f, s2 = 0.f;
#pragma unroll
    for (int k = 0; k < 4; k++) { s1 += t0[k] + t1[k]; s2 += t0[k] * t0[k] + t1[k] * t1[k]; }
#pragma unroll
    for (int off = 16; off; off >>= 1) {
        s1 += __shfl_xor_sync(0xffffffffu, s1, off);
        s2 += __shfl_xor_sync(0xffffffffu, s2, off);
    }
    float mu = s1 * (1.f / 256.f);
    float var = s2 * (1.f / 256.f) - mu * mu;
    float rs = rsqrtf(var + 1e-5f);
    float4 gg0 = *(const float4*)(g0 + ch0),  gg1 = *(const float4*)(g0 + ch1);
    float4 ee0 = *(const float4*)(be0 + ch0), ee1 = *(const float4*)(be0 + ch1);
    // reconstruct residual h = hhi + hlo (exact split)
    size_t o0 = (size_t)d * 256 + ch0, o1 = (size_t)d * 256 + ch1;
    __nv_bfloat162 ph0a = *(const __nv_bfloat162*)(g_hhi + o0);
    __nv_bfloat162 ph0b = *(const __nv_bfloat162*)(g_hhi + o0 + 2);
    __nv_bfloat162 pl0a = *(const __nv_bfloat162*)(g_hlo + o0);
    __nv_bfloat162 pl0b = *(const __nv_bfloat162*)(g_hlo + o0 + 2);
    __nv_bfloat162 ph1a = *(const __nv_bfloat162*)(g_hhi + o1);
    __nv_bfloat162 ph1b = *(const __nv_bfloat162*)(g_hhi + o1 + 2);
    __nv_bfloat162 pl1a = *(const __nv_bfloat162*)(g_hlo + o1);
    __nv_bfloat162 pl1b = *(const __nv_bfloat162*)(g_hlo + o1 + 2);
    float hh0[4] = {
        __bfloat162float(ph0a.x) + __bfloat162float(pl0a.x),
        __bfloat162float(ph0a.y) + __bfloat162float(pl0a.y),
        __bfloat162float(ph0b.x) + __bfloat162float(pl0b.x),
        __bfloat162float(ph0b.y) + __bfloat162float(pl0b.y)};
    float hh1[4] = {
        __bfloat162float(ph1a.x) + __bfloat162float(pl1a.x),
        __bfloat162float(ph1a.y) + __bfloat162float(pl1a.y),
        __bfloat162float(ph1b.x) + __bfloat162float(pl1b.x),
        __bfloat162float(ph1b.y) + __bfloat162float(pl1b.y)};
    float gg0a[4] = {gg0.x, gg0.y, gg0.z, gg0.w};
    float ee0a[4] = {ee0.x, ee0.y, ee0.z, ee0.w};
    float gg1a[4] = {gg1.x, gg1.y, gg1.z, gg1.w};
    float ee1a[4] = {ee1.x, ee1.y, ee1.z, ee1.w};
    float y0[4], y1[4];
#pragma unroll
    for (int k = 0; k < 4; k++) {
        y0[k] = fmaxf((t0[k] - mu) * rs * gg0a[k] + ee0a[k] + hh0[k], 0.f);
        y1[k] = fmaxf((t1[k] - mu) * rs * gg1a[k] + ee1a[k] + hh1[k], 0.f);
    }
    __nv_bfloat16 h[8], l[8];
#pragma unroll
    for (int k = 0; k < 4; k++) { f2hilo(y0[k], h[k], l[k]); f2hilo(y1[k], h[4 + k], l[4 + k]); }
    *(__nv_bfloat162*)(g_h1hi + o0)     = __nv_bfloat162(h[0], h[1]);
    *(__nv_bfloat162*)(g_h1hi + o0 + 2) = __nv_bfloat162(h[2], h[3]);
    *(__nv_bfloat162*)(g_h1hi + o1)     = __nv_bfloat162(h[4], h[5]);
    *(__nv_bfloat162*)(g_h1hi + o1 + 2) = __nv_bfloat162(h[6], h[7]);
    *(__nv_bfloat162*)(g_h1lo + o0)     = __nv_bfloat162(l[0], l[1]);
    *(__nv_bfloat162*)(g_h1lo + o0 + 2) = __nv_bfloat162(l[2], l[3]);
    *(__nv_bfloat162*)(g_h1lo + o1)     = __nv_bfloat162(l[4], l[5]);
    *(__nv_bfloat162*)(g_h1lo + o1 + 2) = __nv_bfloat162(l[6], l[7]);
}

// ============  aggregation layer 1 + fused bias/LN/hilo  ============
__global__ void k_agg1(const float* __restrict__ b1, const float* __restrict__ g1,
                       const float* __restrict__ be1) {
    int d = (blockIdx.x * blockDim.x + threadIdx.x) >> 5;
    int lane = threadIdx.x & 31;
    if (d >= NN) return;
    int beg = g_rowstart[d], end = g_rowstart[d + 1];
    float ald = g_al1[d * 2 + 1];
    float4 acc = {0, 0, 0, 0};
    float den_l = 0.f;
    for (int i = beg; i < end; i += 32) {
        int ii = i + lane;
        int s_i = 0; float w_i = 0.f;
        if (ii < end) {
            s_i = g_esrc[ii];
            float e = g_al1[s_i * 2] + ald;
            e = (e > 0.f) ? e : 0.2f * e;
            w_i = __expf(e);
            den_l += w_i;
        }
        int cnt = min(32, end - i);
        for (int k = 0; k < cnt; k++) {
            float w = __shfl_sync(0xffffffffu, w_i, k);
            int   s = __shfl_sync(0xffffffffu, s_i, k);
            float4 v = *(const float4*)&g_xw1[(size_t)s * 128 + lane * 4];
            acc.x += w * v.x; acc.y += w * v.y; acc.z += w * v.z; acc.w += w * v.w;
        }
    }
    float den = den_l;
#pragma unroll
    for (int off = 16; off; off >>= 1)
        den += __shfl_xor_sync(0xffffffffu, den, off);
    float r = 1.f / den;
    int ch = lane * 4;
    float4 bb = *(const float4*)(b1 + ch);
    float t[4] = {acc.x * r + bb.x, acc.y * r + bb.y, acc.z * r + bb.z, acc.w * r + bb.w};
    float s1 = 0.f, s2 = 0.f;
#pragma unroll
    for (int k = 0; k < 4; k++) { s1 += t[k]; s2 += t[k] * t[k]; }
#pragma unroll
    for (int off = 16; off; off >>= 1) {
        s1 += __shfl_xor_sync(0xffffffffu, s1, off);
        s2 += __shfl_xor_sync(0xffffffffu, s2, off);
    }
    float mu = s1 * (1.f / 128.f);
    float var = s2 * (1.f / 128.f) - mu * mu;
    float rs = rsqrtf(var + 1e-5f);
    float4 gg = *(const float4*)(g1 + ch);
    float4 ee = *(const float4*)(be1 + ch);
    float y[4] = {
        (t[0] - mu) * rs * gg.x + ee.x, (t[1] - mu) * rs * gg.y + ee.y,
        (t[2] - mu) * rs * gg.z + ee.z, (t[3] - mu) * rs * gg.w + ee.w};
    __nv_bfloat16 h[4], l[4];
#pragma unroll
    for (int k = 0; k < 4; k++) f2hilo(y[k], h[k], l[k]);
    size_t o = (size_t)d * 128 + ch;
    *(__nv_bfloat162*)(g_h2hi + o)     = __nv_bfloat162(h[0], h[1]);
    *(__nv_bfloat162*)(g_h2hi + o + 2) = __nv_bfloat162(h[2], h[3]);
    *(__nv_bfloat162*)(g_h2lo + o)     = __nv_bfloat162(l[0], l[1]);
    *(__nv_bfloat162*)(g_h2lo + o + 2) = __nv_bfloat162(l[2], l[3]);
}

// =====================  launch (serial, default stream only)  =====================
extern "C" void kernel_launch(void* const* d_in, const int* in_sizes, int n_in,
                              void* d_out, int out_size) {
    const float* x   = (const float*)d_in[0];
    const void*  ei  = d_in[1];
    const float* Wp  = (const float*)d_in[2];
    const float* bp  = (const float*)d_in[3];
    const float* W0  = (const float*)d_in[4];
    const float* as0 = (const float*)d_in[5];
    const float* ad0 = (const float*)d_in[6];
    const float* b0  = (const float*)d_in[7];
    const float* W1  = (const float*)d_in[8];
    const float* as1 = (const float*)d_in[9];
    const float* ad1 = (const float*)d_in[10];
    const float* b1  = (const float*)d_in[11];
    const float* g0  = (const float*)d_in[12];
    const float* be0 = (const float*)d_in[13];
    const float* g1  = (const float*)d_in[14];
    const float* be1 = (const float*)d_in[15];
    const float* Wo  = (const float*)d_in[16];
    const float* bo  = (const float*)d_in[17];
    float* out = (float*)d_out;

    void *p_xw, *p_xw1;
    void *p_xhi, *p_xlo, *p_hhi, *p_hlo, *p_h1hi, *p_h1lo, *p_h2hi, *p_h2lo;
    void *p_WpThi, *p_WpTlo, *p_W0Thi, *p_W0Tlo, *p_W1Thi, *p_W1Tlo, *p_WoThi, *p_WoTlo;
    cudaGetSymbolAddress(&p_xw,   g_xw);
    cudaGetSymbolAddress(&p_xw1,  g_xw1);
    cudaGetSymbolAddress(&p_xhi,  g_xhi);   cudaGetSymbolAddress(&p_xlo,  g_xlo);
    cudaGetSymbolAddress(&p_hhi,  g_hhi);   cudaGetSymbolAddress(&p_hlo,  g_hlo);
    cudaGetSymbolAddress(&p_h1hi, g_h1hi);  cudaGetSymbolAddress(&p_h1lo, g_h1lo);
    cudaGetSymbolAddress(&p_h2hi, g_h2hi);  cudaGetSymbolAddress(&p_h2lo, g_h2lo);
    cudaGetSymbolAddress(&p_WpThi, g_WpThi); cudaGetSymbolAddress(&p_WpTlo, g_WpTlo);
    cudaGetSymbolAddress(&p_W0Thi, g_W0Thi); cudaGetSymbolAddress(&p_W0Tlo, g_W0Tlo);
    cudaGetSymbolAddress(&p_W1Thi, g_W1Thi); cudaGetSymbolAddress(&p_W1Tlo, g_W1Tlo);
    cudaGetSymbolAddress(&p_WoThi, g_WoThi); cudaGetSymbolAddress(&p_WoTlo, g_WoTlo);

    const int nodeBlocks = (NN + 7) / 8;
    const int edgeBlocks = (ETOT + 255) / 256;
    const int gB128 = (NN + 127) / 128;
    const int gB64  = (NN + 63) / 64;

    cudaFuncSetAttribute((const void*)k_gemm_mma<true,  true,  true,  false, 0, 128>,
                         cudaFuncAttributeMaxDynamicSharedMemorySize, SMEM_G128);
    cudaFuncSetAttribute((const void*)k_gemm_mma<false, false, false, false, 4, 128>,
                         cudaFuncAttributeMaxDynamicSharedMemorySize, SMEM_G128);
    cudaFuncSetAttribute((const void*)k_gemm_mma<false, false, false, false, 1, 64>,
                         cudaFuncAttributeMaxDynamicSharedMemorySize, SMEM_G64);
    cudaFuncSetAttribute((const void*)k_gemm_mma<false, true,  false, true,  0, 64>,
                         cudaFuncAttributeMaxDynamicSharedMemorySize, SMEM_G64);

    // ordered so GEMM1 lands in the profiled slot
    k_init<<<400, 256>>>();
    k_cvtA<<<(NN * 64 + 255) / 256, 256>>>(x, (__nv_bfloat16*)p_xhi, (__nv_bfloat16*)p_xlo, NN * 64);
    k_cvtWall<<<(180224 + 255) / 256, 256>>>(Wp, W0, W1, Wo);

    // GEMM1: h = relu(x@Wp + bp) -> bf16 hi/lo ONLY (no fp32 store)
    k_gemm_mma<true, true, true, false, 0, 128><<<dim3(gB128, 2), 256, SMEM_G128>>>(
        (const __nv_bfloat16*)p_xhi, (const __nv_bfloat16*)p_xlo,
        (const __nv_bfloat16*)p_WpThi, (const __nv_bfloat16*)p_WpTlo,
        bp, nullptr, (__nv_bfloat16*)p_hhi, (__nv_bfloat16*)p_hlo,
        nullptr, nullptr, NN, 256, 256);

    // CSR build (serial)
    k_detect<<<400, 256>>>((const long long*)ei);
    k_count<<<edgeBlocks, 256>>>(ei);
    k_scan1<<<SCANB, 256>>>();
    k_scan2<<<SCANB, 256>>>();
    k_scatter<<<edgeBlocks, 256>>>(ei);

    // GEMM2: xw = h@W0, logits al0 fused
    k_gemm_mma<false, false, false, false, 4, 128><<<dim3(gB128, 2), 256, SMEM_G128>>>(
        (const __nv_bfloat16*)p_hhi, (const __nv_bfloat16*)p_hlo,
        (const __nv_bfloat16*)p_W0Thi, (const __nv_bfloat16*)p_W0Tlo,
        nullptr, (float*)p_xw, nullptr, nullptr, as0, ad0, NN, 256, 256);

    // agg0 + LN0 + residual + relu -> h1 hi/lo
    k_agg0<<<nodeBlocks, 256>>>(b0, g0, be0);

    // GEMM3 (64-row tiles): xw1 = h1@W1, logits al1 fused
    k_gemm_mma<false, false, false, false, 1, 64><<<dim3(gB64, 1), 256, SMEM_G64>>>(
        (const __nv_bfloat16*)p_h1hi, (const __nv_bfloat16*)p_h1lo,
        (const __nv_bfloat16*)p_W1Thi, (const __nv_bfloat16*)p_W1Tlo,
        nullptr, (float*)p_xw1, nullptr, nullptr, as1, ad1, NN, 256, 128);

    // agg1 + LN1 -> h2 hi/lo
    k_agg1<<<nodeBlocks, 256>>>(b1, g1, be1);

    // GEMM4 (64-row tiles): out = rownorm(h2@Wo + bo)
    k_gemm_mma<false, true, false, true, 0, 64><<<dim3(gB64, 1), 256, SMEM_G64>>>(
        (const __nv_bfloat16*)p_h2hi, (const __nv_bfloat16*)p_h2lo,
        (const __nv_bfloat16*)p_WoThi, (const __nv_bfloat16*)p_WoTlo,
        bo, out, nullptr, nullptr, nullptr, nullptr, NN, 128, 128);
}